// round 15
// baseline (speedup 1.0000x reference)
#include <cuda_runtime.h>
#include <cuda_fp16.h>
#include <cstdint>

#define BATCH 32
#define HDIM  56
#define WDIM  56
#define CIN   256
#define COUT  256
#define HP    58
#define WP    58
#define MTOT  (BATCH*HDIM*WDIM)        // 100352
#define NPIX_PAD (BATCH*HP*WP)         // 107648
#define NCHUNK 36                      // 9 taps * 4 chunks of 64 channels
#define NSTAGE 3

// stage: A 8KB | B 16KB | pad -> 26KB. 3 stages = 78KB/CTA; 2 CTAs = 156KB fits,
// 3 CTAs = 234KB > 227KB max -> occupancy pinned at 2 (intentional: W=10.59 waves).
#define STAGE_BYTES 26624
#define B_OFF 8192

// padded activations, fp16: [pix][4 chunks][64ch * 2B] = 512B/pixel
__device__ __align__(1024) unsigned char g_apad[(size_t)NPIX_PAD * 512];
// packed weights fp16: [tap 9][chunk 4][co 256][64ch * 2B = 128B]
__device__ __align__(1024) unsigned char g_bpack[9*4*256*128];

// ---------------- prep kernels ----------------
// 4 pixels per 128-thread block; 32 threads x 8 channels each; 16B stores.
__global__ void prep_a_kernel(const float* __restrict__ in) {
    const int t   = threadIdx.x;
    const int pix = blockIdx.x * 4 + (t >> 5);
    const int tt  = t & 31;
    const int b   = pix / (HP*WP);
    const int rr  = pix % (HP*WP);
    const int yp  = rr / WP, xp = rr % WP;
    const int c0  = tt * 8;               // 0..248
    const int chunk = c0 >> 6, i = c0 & 63;
    uint4 w = make_uint4(0u, 0u, 0u, 0u);
    if (!(yp == 0 || yp == HP-1 || xp == 0 || xp == WP-1)) {
        const float* p = in + ((size_t)((b*HDIM + (yp-1))*WDIM + (xp-1)))*CIN + c0;
        const float4 v0 = *(const float4*)(p);
        const float4 v1 = *(const float4*)(p + 4);
        __half2 h;
        h = __floats2half2_rn(v0.x, v0.y); w.x = *(unsigned*)&h;
        h = __floats2half2_rn(v0.z, v0.w); w.y = *(unsigned*)&h;
        h = __floats2half2_rn(v1.x, v1.y); w.z = *(unsigned*)&h;
        h = __floats2half2_rn(v1.z, v1.w); w.w = *(unsigned*)&h;
    }
    *(uint4*)(g_apad + (size_t)pix*512 + chunk*128 + i*2) = w;
}

__global__ void prep_b_kernel(const float* __restrict__ wt) {
    const int k  = blockIdx.x;       // 0..2303 : (ky*3+kx)*256 + ci
    const int co = threadIdx.x;      // 0..255
    const float v = wt[(size_t)k*COUT + co];
    __half h = __float2half_rn(v);
    const int tap = k >> 8, ci = k & 255;
    const int chunk = ci >> 6, i = ci & 63;
    *(unsigned short*)(g_bpack + ((size_t)((tap*4 + chunk)*256 + co))*128 + i*2)
        = *(unsigned short*)&h;
}

// ---------------- device helpers ----------------
__device__ __forceinline__ uint32_t smem_u32(const void* p) {
    uint32_t a;
    asm("{ .reg .u64 t; cvta.to.shared.u64 t, %1; cvt.u32.u64 %0, t; }" : "=r"(a) : "l"(p));
    return a;
}

#define LDSM4(r0,r1,r2,r3,addr) \
    asm volatile("ldmatrix.sync.aligned.m8n8.x4.shared.b16 {%0,%1,%2,%3}, [%4];" \
        : "=r"(r0), "=r"(r1), "=r"(r2), "=r"(r3) : "r"(addr))

__device__ __forceinline__ void mma16816(float* c, const uint32_t* a, const uint32_t* b) {
    asm volatile(
        "mma.sync.aligned.m16n8k16.row.col.f32.f16.f16.f32 "
        "{%0,%1,%2,%3}, {%4,%5,%6,%7}, {%8,%9}, {%0,%1,%2,%3};"
        : "+f"(c[0]), "+f"(c[1]), "+f"(c[2]), "+f"(c[3])
        : "r"(a[0]), "r"(a[1]), "r"(a[2]), "r"(a[3]), "r"(b[0]), "r"(b[1]));
}

// ---------------- main conv kernel ----------------
// CTA tile 64x128; 128 threads = 4 warps in 2(M)x2(N); warp tile 32x64.
// Fragment double-buffering: LDSM for kh+1 overlaps MMAs of kh.
__global__ void __launch_bounds__(128, 2) conv_mma_kernel(
    const float* __restrict__ bias, float* __restrict__ out)
{
    extern __shared__ unsigned char smem[];
    const uint32_t sb = smem_u32(smem);
    const int t = threadIdx.x;
    const int lane = t & 31, warp = t >> 5;
    const int bm = blockIdx.y * 64;
    const int bn = blockIdx.x * 128;
    const int m0 = (warp >> 1) * 32;     // 2 m-warps
    const int n0 = (warp & 1) * 64;      // 2 n-warps

    // ---- loader setup: t<64 -> A row bm+t; all threads -> B row bn+t ----
    const unsigned char* gA = nullptr;
    if (t < 64) {
        const int m  = bm + t;
        const int b  = m / (HDIM*WDIM);
        const int r2 = m % (HDIM*WDIM);
        const int y  = r2 / WDIM, x = r2 % WDIM;
        gA = g_apad + (size_t)((b*HP + y)*WP + x) * 512;
    }
    const unsigned char* gB = g_bpack + ((size_t)(bn + t)) * 128;
    const uint32_t swz = (uint32_t)((t & 7) << 4);

    auto load_chunk = [&](int c, int stg) {
        const int tap = c >> 2;
        const unsigned char* bsrc = gB + (size_t)c * (256*128);
        const uint32_t base = sb + stg*STAGE_BYTES;
        if (t < 64) {
            const unsigned char* asrc = gA + (size_t)((tap/3)*WP + (tap%3))*512 + (c & 3)*128;
            const uint32_t adst = base + (uint32_t)t*128;
            #pragma unroll
            for (int j = 0; j < 8; j++) {
                const uint32_t o = ((uint32_t)(j*16)) ^ swz;
                asm volatile("cp.async.cg.shared.global [%0], [%1], 16;"
                             :: "r"(adst + o), "l"(asrc + j*16) : "memory");
            }
        }
        const uint32_t bdst = base + B_OFF + (uint32_t)t*128;
        #pragma unroll
        for (int j = 0; j < 8; j++) {
            const uint32_t o = ((uint32_t)(j*16)) ^ swz;
            asm volatile("cp.async.cg.shared.global [%0], [%1], 16;"
                         :: "r"(bdst + o), "l"(bsrc + j*16) : "memory");
        }
        asm volatile("cp.async.commit_group;" ::: "memory");
    };

    // ---- ldmatrix lane addressing ----
    const uint32_t lr   = (uint32_t)(lane & 15);
    const uint32_t koff = (uint32_t)((lane >> 4) << 4);
    const uint32_t xorv = (uint32_t)((lane & 7) << 4);

    // fragment load for one kh slice into given buffers
    auto ldsm_slice = [&](uint32_t Ab, uint32_t Bb, int kh,
                          uint32_t (*ah)[4], uint32_t (*bh)[2]) {
        const uint32_t chi = (uint32_t)(kh*32) + koff;
        #pragma unroll
        for (int mi = 0; mi < 2; mi++) {
            const uint32_t r = Ab + (uint32_t)(m0 + mi*16 + lr)*128;
            LDSM4(ah[mi][0], ah[mi][1], ah[mi][2], ah[mi][3], r + (chi ^ xorv));
        }
        #pragma unroll
        for (int nb = 0; nb < 4; nb++) {
            const uint32_t r = Bb + (uint32_t)(n0 + nb*16 + lr)*128;
            uint32_t b0, b1, b2, b3;
            LDSM4(b0, b1, b2, b3, r + (chi ^ xorv));
            bh[nb*2][0] = b0; bh[nb*2][1] = b2;
            bh[nb*2+1][0] = b1; bh[nb*2+1][1] = b3;
        }
    };

    float acc[2][8][4];
    #pragma unroll
    for (int i = 0; i < 2; i++)
        #pragma unroll
        for (int j = 0; j < 8; j++)
            #pragma unroll
            for (int k = 0; k < 4; k++) acc[i][j][k] = 0.f;

    // prologue: 2 chunks in flight
    load_chunk(0, 0);
    load_chunk(1, 1);

    uint32_t ah[2][2][4], bh[2][8][2];

    int stg = 0;        // stage of chunk c
    #pragma unroll 1
    for (int c = 0; c < NCHUNK; c++) {
        if (c == NCHUNK - 1)
            asm volatile("cp.async.wait_group 0;" ::: "memory");
        else
            asm volatile("cp.async.wait_group 1;" ::: "memory");
        __syncthreads();   // single barrier per chunk: also releases stage (c+2)%3,
                           // whose readers (chunk c-1) finished before this point.

        const uint32_t Ab = sb + stg*STAGE_BYTES;
        const uint32_t Bb = Ab + B_OFF;

        // prefetch kh=0 fragments
        ldsm_slice(Ab, Bb, 0, ah[0], bh[0]);

        #pragma unroll
        for (int kh = 0; kh < 4; kh++) {
            const int cur = kh & 1, nxt = cur ^ 1;
            if (kh < 3)
                ldsm_slice(Ab, Bb, kh + 1, ah[nxt], bh[nxt]);
            if (kh == 2 && c + 2 < NCHUNK) {
                int ns = stg + 2; if (ns >= NSTAGE) ns -= NSTAGE;
                load_chunk(c + 2, ns);
            }
            #pragma unroll
            for (int mi = 0; mi < 2; mi++)
                #pragma unroll
                for (int ni = 0; ni < 8; ni++)
                    mma16816(acc[mi][ni], ah[cur][mi], bh[cur][ni]);
        }

        if (++stg == NSTAGE) stg = 0;
    }

    // ---- epilogue ----
    const int g = lane >> 2, q = lane & 3;
    #pragma unroll
    for (int ni = 0; ni < 8; ni++) {
        const int ncol = bn + n0 + ni*8 + q*2;
        const float2 bv = *(const float2*)(bias + ncol);
        #pragma unroll
        for (int mi = 0; mi < 2; mi++) {
            const int mrow = bm + m0 + mi*16 + g;
            float2 o0, o1;
            o0.x = acc[mi][ni][0] + bv.x; o0.y = acc[mi][ni][1] + bv.y;
            o1.x = acc[mi][ni][2] + bv.x; o1.y = acc[mi][ni][3] + bv.y;
            *(float2*)(out + (size_t)mrow*COUT + ncol)       = o0;
            *(float2*)(out + (size_t)(mrow+8)*COUT + ncol)   = o1;
        }
    }
}

// ---------------- launch ----------------
extern "C" void kernel_launch(void* const* d_in, const int* in_sizes, int n_in,
                              void* d_out, int out_size) {
    const float* in   = (const float*)d_in[0];   // [32,56,56,256] f32
    const float* wt   = (const float*)d_in[1];   // [3,3,256,256]  f32
    const float* bias = (const float*)d_in[2];   // [256]          f32
    float* out = (float*)d_out;

    static int smem_set = 0;
    if (!smem_set) {
        cudaFuncSetAttribute(conv_mma_kernel,
                             cudaFuncAttributeMaxDynamicSharedMemorySize, NSTAGE*STAGE_BYTES);
        smem_set = 1;
    }

    prep_a_kernel<<<NPIX_PAD/4, 128>>>(in);
    prep_b_kernel<<<9*256, 256>>>(wt);
    dim3 grid(2, MTOT/64);   // (2, 1568) = 3136 CTAs
    conv_mma_kernel<<<grid, 128, NSTAGE*STAGE_BYTES>>>(bias, out);
}

// round 16
// speedup vs baseline: 1.1682x; 1.1682x over previous
#include <cuda_runtime.h>
#include <cuda_fp16.h>
#include <cstdint>

#define BATCH 32
#define HDIM  56
#define WDIM  56
#define CIN   256
#define COUT  256
#define HP    58
#define WP    58
#define MTOT  (BATCH*HDIM*WDIM)        // 100352
#define NPIX_PAD (BATCH*HP*WP)         // 107648
#define NCHUNK 36                      // 9 taps * 4 chunks of 64 channels
#define NSTAGE 3

#define STAGE_BYTES 32768              // A 16KB | B 16KB

// padded activations, fp16: [pix][4 chunks][64ch * 2B] = 512B/pixel
__device__ __align__(1024) unsigned char g_apad[(size_t)NPIX_PAD * 512];
// packed weights fp16: [tap 9][chunk 4][co 256][64ch * 2B = 128B]
__device__ __align__(1024) unsigned char g_bpack[9*4*256*128];

// ---------------- prep kernels ----------------
// 4 pixels per 128-thread block; 32 threads x 8 channels each; 16B stores.
__global__ void prep_a_kernel(const float* __restrict__ in) {
    const int t   = threadIdx.x;
    const int pix = blockIdx.x * 4 + (t >> 5);
    const int tt  = t & 31;
    const int b   = pix / (HP*WP);
    const int rr  = pix % (HP*WP);
    const int yp  = rr / WP, xp = rr % WP;
    const int c0  = tt * 8;               // 0..248
    const int chunk = c0 >> 6, i = c0 & 63;
    uint4 w = make_uint4(0u, 0u, 0u, 0u);
    if (!(yp == 0 || yp == HP-1 || xp == 0 || xp == WP-1)) {
        const float* p = in + ((size_t)((b*HDIM + (yp-1))*WDIM + (xp-1)))*CIN + c0;
        const float4 v0 = *(const float4*)(p);
        const float4 v1 = *(const float4*)(p + 4);
        __half2 h;
        h = __floats2half2_rn(v0.x, v0.y); w.x = *(unsigned*)&h;
        h = __floats2half2_rn(v0.z, v0.w); w.y = *(unsigned*)&h;
        h = __floats2half2_rn(v1.x, v1.y); w.z = *(unsigned*)&h;
        h = __floats2half2_rn(v1.z, v1.w); w.w = *(unsigned*)&h;
    }
    *(uint4*)(g_apad + (size_t)pix*512 + chunk*128 + i*2) = w;
}

__global__ void prep_b_kernel(const float* __restrict__ wt) {
    const int k  = blockIdx.x;       // 0..2303 : (ky*3+kx)*256 + ci
    const int co = threadIdx.x;      // 0..255
    const float v = wt[(size_t)k*COUT + co];
    __half h = __float2half_rn(v);
    const int tap = k >> 8, ci = k & 255;
    const int chunk = ci >> 6, i = ci & 63;
    *(unsigned short*)(g_bpack + ((size_t)((tap*4 + chunk)*256 + co))*128 + i*2)
        = *(unsigned short*)&h;
}

// ---------------- device helpers ----------------
__device__ __forceinline__ uint32_t smem_u32(const void* p) {
    uint32_t a;
    asm("{ .reg .u64 t; cvta.to.shared.u64 t, %1; cvt.u32.u64 %0, t; }" : "=r"(a) : "l"(p));
    return a;
}

#define LDSM4(r0,r1,r2,r3,addr) \
    asm volatile("ldmatrix.sync.aligned.m8n8.x4.shared.b16 {%0,%1,%2,%3}, [%4];" \
        : "=r"(r0), "=r"(r1), "=r"(r2), "=r"(r3) : "r"(addr))

__device__ __forceinline__ void mma16816(float* c, const uint32_t* a, const uint32_t* b) {
    asm volatile(
        "mma.sync.aligned.m16n8k16.row.col.f32.f16.f16.f32 "
        "{%0,%1,%2,%3}, {%4,%5,%6,%7}, {%8,%9}, {%0,%1,%2,%3};"
        : "+f"(c[0]), "+f"(c[1]), "+f"(c[2]), "+f"(c[3])
        : "r"(a[0]), "r"(a[1]), "r"(a[2]), "r"(a[3]), "r"(b[0]), "r"(b[1]));
}

// ---------------- main conv kernel ----------------
// CTA tile 128x128; 128 threads = 4 warps in 2x2; warp tile 64x64.
// Fragment double-buffering across kh slices AND across chunks: the kh0
// fragments of chunk c+1 are prefetched during chunk c's kh3 phase, so no
// ldmatrix is ever exposed right after the barrier.
__global__ void __launch_bounds__(128, 2) conv_mma_kernel(
    const float* __restrict__ bias, float* __restrict__ out)
{
    extern __shared__ unsigned char smem[];
    const uint32_t sb = smem_u32(smem);
    const int t = threadIdx.x;
    const int lane = t & 31, warp = t >> 5;
    const int bm = blockIdx.y * 128;
    const int bn = blockIdx.x * 128;
    const int m0 = (warp >> 1) * 64;     // 2 m-warps
    const int n0 = (warp & 1) * 64;      // 2 n-warps

    // ---- loader setup: every thread loads A row t AND B row t ----
    const int m  = bm + t;
    const int b  = m / (HDIM*WDIM);
    const int r2 = m % (HDIM*WDIM);
    const int y  = r2 / WDIM, x = r2 % WDIM;
    const unsigned char* gA = g_apad + (size_t)((b*HP + y)*WP + x) * 512;
    const unsigned char* gB = g_bpack + ((size_t)(bn + t)) * 128;
    const uint32_t swz = (uint32_t)((t & 7) << 4);

    auto load_chunk = [&](int c, int stg) {
        const int tap = c >> 2;
        const unsigned char* asrc = gA + (size_t)((tap/3)*WP + (tap%3))*512 + (c & 3)*128;
        const unsigned char* bsrc = gB + (size_t)c * (256*128);
        const uint32_t adst = sb + stg*STAGE_BYTES + (uint32_t)t*128;
        const uint32_t bdst = adst + 16384;
        #pragma unroll
        for (int j = 0; j < 8; j++) {
            const uint32_t o = ((uint32_t)(j*16)) ^ swz;
            asm volatile("cp.async.cg.shared.global [%0], [%1], 16;"
                         :: "r"(adst + o), "l"(asrc + j*16) : "memory");
            asm volatile("cp.async.cg.shared.global [%0], [%1], 16;"
                         :: "r"(bdst + o), "l"(bsrc + j*16) : "memory");
        }
        asm volatile("cp.async.commit_group;" ::: "memory");
    };

    // ---- ldmatrix lane addressing ----
    const uint32_t lr   = (uint32_t)(lane & 15);
    const uint32_t koff = (uint32_t)((lane >> 4) << 4);
    const uint32_t xorv = (uint32_t)((lane & 7) << 4);

    auto ldsm_slice = [&](uint32_t Ab, uint32_t Bb, int kh,
                          uint32_t (*ah)[4], uint32_t (*bh)[2]) {
        const uint32_t chi = (uint32_t)(kh*32) + koff;
        #pragma unroll
        for (int mi = 0; mi < 4; mi++) {
            const uint32_t r = Ab + (uint32_t)(m0 + mi*16 + lr)*128;
            LDSM4(ah[mi][0], ah[mi][1], ah[mi][2], ah[mi][3], r + (chi ^ xorv));
        }
        #pragma unroll
        for (int nb = 0; nb < 4; nb++) {
            const uint32_t r = Bb + (uint32_t)(n0 + nb*16 + lr)*128;
            uint32_t b0, b1, b2, b3;
            LDSM4(b0, b1, b2, b3, r + (chi ^ xorv));
            bh[nb*2][0] = b0; bh[nb*2][1] = b2;
            bh[nb*2+1][0] = b1; bh[nb*2+1][1] = b3;
        }
    };

    float acc[4][8][4];
    #pragma unroll
    for (int i = 0; i < 4; i++)
        #pragma unroll
        for (int j = 0; j < 8; j++)
            #pragma unroll
            for (int k = 0; k < 4; k++) acc[i][j][k] = 0.f;

    // prologue: 2 chunks in flight; chunk 0 complete before first fragment load
    load_chunk(0, 0);
    load_chunk(1, 1);
    asm volatile("cp.async.wait_group 1;" ::: "memory");
    __syncthreads();

    uint32_t ah[2][4][4], bh[2][8][2];
    ldsm_slice(sb, sb + 16384, 0, ah[0], bh[0]);   // chunk 0, kh0 -> buf 0

    int stg = 0;        // stage of chunk c
    #pragma unroll 1
    for (int c = 0; c < NCHUNK; c++) {
        const uint32_t Ab = sb + stg*STAGE_BYTES;
        const uint32_t Bb = Ab + 16384;
        int stg1 = stg + 1; if (stg1 >= NSTAGE) stg1 -= NSTAGE;
        int stg2 = stg + 2; if (stg2 >= NSTAGE) stg2 -= NSTAGE;

        #pragma unroll
        for (int kh = 0; kh < 4; kh++) {
            const int cur = kh & 1, nxt = cur ^ 1;

            // prefetch the next slice's fragments (current stage, pre-barrier)
            if (kh < 3)
                ldsm_slice(Ab, Bb, kh + 1, ah[nxt], bh[nxt]);

            // kh3: prefetch chunk c+1's kh0 fragments (stage stg1). Data was
            // made visible by the wait_group+barrier in the kh2 phase below.
            if (kh == 3 && c + 1 < NCHUNK)
                ldsm_slice(sb + stg1*STAGE_BYTES, sb + stg1*STAGE_BYTES + 16384,
                           0, ah[0], bh[0]);

            #pragma unroll
            for (int mi = 0; mi < 4; mi++)
                #pragma unroll
                for (int ni = 0; ni < 8; ni++)
                    mma16816(acc[mi][ni], ah[cur][mi], bh[cur][ni]);

            // kh2 (after its MMAs are issued): drain chunk c+1's group (the
            // only one in flight -> no stall), make its data CTA-visible,
            // then issue chunk c+2's loads into the stage chunk c-1 vacated.
            if (kh == 2 && c + 1 < NCHUNK) {
                asm volatile("cp.async.wait_group 0;" ::: "memory");
                __syncthreads();
                if (c + 2 < NCHUNK)
                    load_chunk(c + 2, stg2);
            }
        }

        stg = stg1;
    }

    // ---- epilogue ----
    const int g = lane >> 2, q = lane & 3;
    #pragma unroll
    for (int ni = 0; ni < 8; ni++) {
        const int ncol = bn + n0 + ni*8 + q*2;
        const float2 bv = *(const float2*)(bias + ncol);
        #pragma unroll
        for (int mi = 0; mi < 4; mi++) {
            const int mrow = bm + m0 + mi*16 + g;
            float2 o0, o1;
            o0.x = acc[mi][ni][0] + bv.x; o0.y = acc[mi][ni][1] + bv.y;
            o1.x = acc[mi][ni][2] + bv.x; o1.y = acc[mi][ni][3] + bv.y;
            *(float2*)(out + (size_t)mrow*COUT + ncol)       = o0;
            *(float2*)(out + (size_t)(mrow+8)*COUT + ncol)   = o1;
        }
    }
}

// ---------------- launch ----------------
extern "C" void kernel_launch(void* const* d_in, const int* in_sizes, int n_in,
                              void* d_out, int out_size) {
    const float* in   = (const float*)d_in[0];   // [32,56,56,256] f32
    const float* wt   = (const float*)d_in[1];   // [3,3,256,256]  f32
    const float* bias = (const float*)d_in[2];   // [256]          f32
    float* out = (float*)d_out;

    static int smem_set = 0;
    if (!smem_set) {
        cudaFuncSetAttribute(conv_mma_kernel,
                             cudaFuncAttributeMaxDynamicSharedMemorySize, NSTAGE*STAGE_BYTES);
        smem_set = 1;
    }

    prep_a_kernel<<<NPIX_PAD/4, 128>>>(in);
    prep_b_kernel<<<9*256, 256>>>(wt);
    dim3 grid(2, MTOT/128);   // (2, 784) = 1568 CTAs
    conv_mma_kernel<<<grid, 128, NSTAGE*STAGE_BYTES>>>(bias, out);
}

// round 17
// speedup vs baseline: 1.2170x; 1.0418x over previous
#include <cuda_runtime.h>
#include <cuda_fp16.h>
#include <cstdint>

#define BATCH 32
#define HDIM  56
#define WDIM  56
#define CIN   256
#define COUT  256
#define HP    58
#define WP    58
#define MTOT  (BATCH*HDIM*WDIM)        // 100352
#define NPIX_PAD (BATCH*HP*WP)         // 107648
#define NCHUNK 36                      // 9 taps * 4 chunks of 64 channels
#define NSTAGE 3

#define STAGE_BYTES 32768              // A 16KB | B 16KB

// padded activations, fp16: [pix][4 chunks][64ch * 2B] = 512B/pixel
__device__ __align__(1024) unsigned char g_apad[(size_t)NPIX_PAD * 512];
// packed weights fp16: [tap 9][chunk 4][co 256][64ch * 2B = 128B]
__device__ __align__(1024) unsigned char g_bpack[9*4*256*128];

// ---------------- prep kernels ----------------
// 4 pixels per 128-thread block; 32 threads x 8 channels each; 16B stores.
__global__ void prep_a_kernel(const float* __restrict__ in) {
    const int t   = threadIdx.x;
    const int pix = blockIdx.x * 4 + (t >> 5);
    const int tt  = t & 31;
    const int b   = pix / (HP*WP);
    const int rr  = pix % (HP*WP);
    const int yp  = rr / WP, xp = rr % WP;
    const int c0  = tt * 8;               // 0..248
    const int chunk = c0 >> 6, i = c0 & 63;
    uint4 w = make_uint4(0u, 0u, 0u, 0u);
    if (!(yp == 0 || yp == HP-1 || xp == 0 || xp == WP-1)) {
        const float* p = in + ((size_t)((b*HDIM + (yp-1))*WDIM + (xp-1)))*CIN + c0;
        const float4 v0 = *(const float4*)(p);
        const float4 v1 = *(const float4*)(p + 4);
        __half2 h;
        h = __floats2half2_rn(v0.x, v0.y); w.x = *(unsigned*)&h;
        h = __floats2half2_rn(v0.z, v0.w); w.y = *(unsigned*)&h;
        h = __floats2half2_rn(v1.x, v1.y); w.z = *(unsigned*)&h;
        h = __floats2half2_rn(v1.z, v1.w); w.w = *(unsigned*)&h;
    }
    *(uint4*)(g_apad + (size_t)pix*512 + chunk*128 + i*2) = w;
}

// 64 threads/block, 4 c_out per thread: coalesced float4 load along co,
// 4 x 2B stores at 128B stride into the packed layout.
__global__ void prep_b_kernel(const float* __restrict__ wt) {
    const int k   = blockIdx.x;      // 0..2303 : (ky*3+kx)*256 + ci
    const int co0 = threadIdx.x * 4; // 0..252
    const float4 v = *(const float4*)(wt + (size_t)k*COUT + co0);
    const int tap = k >> 8, ci = k & 255;
    const int chunk = ci >> 6, i = ci & 63;
    unsigned char* base = g_bpack + ((size_t)((tap*4 + chunk)*256 + co0))*128 + i*2;
    __half h;
    h = __float2half_rn(v.x); *(unsigned short*)(base)         = *(unsigned short*)&h;
    h = __float2half_rn(v.y); *(unsigned short*)(base + 128)   = *(unsigned short*)&h;
    h = __float2half_rn(v.z); *(unsigned short*)(base + 256)   = *(unsigned short*)&h;
    h = __float2half_rn(v.w); *(unsigned short*)(base + 384)   = *(unsigned short*)&h;
}

// ---------------- device helpers ----------------
__device__ __forceinline__ uint32_t smem_u32(const void* p) {
    uint32_t a;
    asm("{ .reg .u64 t; cvta.to.shared.u64 t, %1; cvt.u32.u64 %0, t; }" : "=r"(a) : "l"(p));
    return a;
}

#define LDSM4(r0,r1,r2,r3,addr) \
    asm volatile("ldmatrix.sync.aligned.m8n8.x4.shared.b16 {%0,%1,%2,%3}, [%4];" \
        : "=r"(r0), "=r"(r1), "=r"(r2), "=r"(r3) : "r"(addr))

__device__ __forceinline__ void mma16816(float* c, const uint32_t* a, const uint32_t* b) {
    asm volatile(
        "mma.sync.aligned.m16n8k16.row.col.f32.f16.f16.f32 "
        "{%0,%1,%2,%3}, {%4,%5,%6,%7}, {%8,%9}, {%0,%1,%2,%3};"
        : "+f"(c[0]), "+f"(c[1]), "+f"(c[2]), "+f"(c[3])
        : "r"(a[0]), "r"(a[1]), "r"(a[2]), "r"(a[3]), "r"(b[0]), "r"(b[1]));
}

// ---------------- main conv kernel ----------------
// (exact R14 configuration: proven 591.5us)
// 128 threads = 4 warps in 2x2; warp tile 64x64; CTA tile 128x128.
// Fragment double-buffering: LDSM for kh+1 overlaps MMAs of kh.
__global__ void __launch_bounds__(128, 2) conv_mma_kernel(
    const float* __restrict__ bias, float* __restrict__ out)
{
    extern __shared__ unsigned char smem[];
    const uint32_t sb = smem_u32(smem);
    const int t = threadIdx.x;
    const int lane = t & 31, warp = t >> 5;
    const int bm = blockIdx.y * 128;
    const int bn = blockIdx.x * 128;
    const int m0 = (warp >> 1) * 64;     // 2 m-warps
    const int n0 = (warp & 1) * 64;      // 2 n-warps

    // ---- loader setup: every thread loads A row t AND B row t ----
    const int m  = bm + t;
    const int b  = m / (HDIM*WDIM);
    const int r2 = m % (HDIM*WDIM);
    const int y  = r2 / WDIM, x = r2 % WDIM;
    const unsigned char* gA = g_apad + (size_t)((b*HP + y)*WP + x) * 512;
    const unsigned char* gB = g_bpack + ((size_t)(bn + t)) * 128;
    const uint32_t swz = (uint32_t)((t & 7) << 4);

    auto load_chunk = [&](int c, int stg) {
        const int tap = c >> 2;
        const unsigned char* asrc = gA + (size_t)((tap/3)*WP + (tap%3))*512 + (c & 3)*128;
        const unsigned char* bsrc = gB + (size_t)c * (256*128);
        const uint32_t adst = sb + stg*STAGE_BYTES + (uint32_t)t*128;
        const uint32_t bdst = adst + 16384;
        #pragma unroll
        for (int j = 0; j < 8; j++) {
            const uint32_t o = ((uint32_t)(j*16)) ^ swz;
            asm volatile("cp.async.cg.shared.global [%0], [%1], 16;"
                         :: "r"(adst + o), "l"(asrc + j*16) : "memory");
            asm volatile("cp.async.cg.shared.global [%0], [%1], 16;"
                         :: "r"(bdst + o), "l"(bsrc + j*16) : "memory");
        }
        asm volatile("cp.async.commit_group;" ::: "memory");
    };

    // ---- ldmatrix lane addressing ----
    const uint32_t lr   = (uint32_t)(lane & 15);
    const uint32_t koff = (uint32_t)((lane >> 4) << 4);
    const uint32_t xorv = (uint32_t)((lane & 7) << 4);

    // fragment load for one kh slice into given buffers
    auto ldsm_slice = [&](uint32_t Ab, uint32_t Bb, int kh,
                          uint32_t (*ah)[4], uint32_t (*bh)[2]) {
        const uint32_t chi = (uint32_t)(kh*32) + koff;
        #pragma unroll
        for (int mi = 0; mi < 4; mi++) {
            const uint32_t r = Ab + (uint32_t)(m0 + mi*16 + lr)*128;
            LDSM4(ah[mi][0], ah[mi][1], ah[mi][2], ah[mi][3], r + (chi ^ xorv));
        }
        #pragma unroll
        for (int nb = 0; nb < 4; nb++) {
            const uint32_t r = Bb + (uint32_t)(n0 + nb*16 + lr)*128;
            uint32_t b0, b1, b2, b3;
            LDSM4(b0, b1, b2, b3, r + (chi ^ xorv));
            bh[nb*2][0] = b0; bh[nb*2][1] = b2;
            bh[nb*2+1][0] = b1; bh[nb*2+1][1] = b3;
        }
    };

    float acc[4][8][4];
    #pragma unroll
    for (int i = 0; i < 4; i++)
        #pragma unroll
        for (int j = 0; j < 8; j++)
            #pragma unroll
            for (int k = 0; k < 4; k++) acc[i][j][k] = 0.f;

    // prologue: 2 chunks in flight
    load_chunk(0, 0);
    load_chunk(1, 1);

    uint32_t ah[2][4][4], bh[2][8][2];

    int stg = 0;        // stage of chunk c
    #pragma unroll 1
    for (int c = 0; c < NCHUNK; c++) {
        if (c == NCHUNK - 1)
            asm volatile("cp.async.wait_group 0;" ::: "memory");
        else
            asm volatile("cp.async.wait_group 1;" ::: "memory");
        __syncthreads();   // single barrier per chunk: also releases stage (c+2)%3,
                           // whose readers (chunk c-1) finished before this point.

        const uint32_t Ab = sb + stg*STAGE_BYTES;
        const uint32_t Bb = Ab + 16384;

        // prefetch kh=0 fragments
        ldsm_slice(Ab, Bb, 0, ah[0], bh[0]);

        #pragma unroll
        for (int kh = 0; kh < 4; kh++) {
            const int cur = kh & 1, nxt = cur ^ 1;
            // prefetch next slice's fragments; independent of cur MMAs,
            // so LDSM latency hides under the tensor-pipe work below.
            if (kh < 3)
                ldsm_slice(Ab, Bb, kh + 1, ah[nxt], bh[nxt]);
            // issue next-next chunk's cp.async away from the kh=0/1 LDSM bursts
            if (kh == 2 && c + 2 < NCHUNK) {
                int ns = stg + 2; if (ns >= NSTAGE) ns -= NSTAGE;
                load_chunk(c + 2, ns);
            }
            #pragma unroll
            for (int mi = 0; mi < 4; mi++)
                #pragma unroll
                for (int ni = 0; ni < 8; ni++)
                    mma16816(acc[mi][ni], ah[cur][mi], bh[cur][ni]);
        }

        if (++stg == NSTAGE) stg = 0;
    }

    // ---- epilogue ----
    const int g = lane >> 2, q = lane & 3;
    #pragma unroll
    for (int ni = 0; ni < 8; ni++) {
        const int ncol = bn + n0 + ni*8 + q*2;
        const float2 bv = *(const float2*)(bias + ncol);
        #pragma unroll
        for (int mi = 0; mi < 4; mi++) {
            const int mrow = bm + m0 + mi*16 + g;
            float2 o0, o1;
            o0.x = acc[mi][ni][0] + bv.x; o0.y = acc[mi][ni][1] + bv.y;
            o1.x = acc[mi][ni][2] + bv.x; o1.y = acc[mi][ni][3] + bv.y;
            *(float2*)(out + (size_t)mrow*COUT + ncol)       = o0;
            *(float2*)(out + (size_t)(mrow+8)*COUT + ncol)   = o1;
        }
    }
}

// ---------------- launch ----------------
extern "C" void kernel_launch(void* const* d_in, const int* in_sizes, int n_in,
                              void* d_out, int out_size) {
    const float* in   = (const float*)d_in[0];   // [32,56,56,256] f32
    const float* wt   = (const float*)d_in[1];   // [3,3,256,256]  f32
    const float* bias = (const float*)d_in[2];   // [256]          f32
    float* out = (float*)d_out;

    static int smem_set = 0;
    if (!smem_set) {
        cudaFuncSetAttribute(conv_mma_kernel,
                             cudaFuncAttributeMaxDynamicSharedMemorySize, NSTAGE*STAGE_BYTES);
        smem_set = 1;
    }

    prep_a_kernel<<<NPIX_PAD/4, 128>>>(in);
    prep_b_kernel<<<9*256, 64>>>(wt);
    dim3 grid(2, MTOT/128);   // (2, 784) = 1568 CTAs
    conv_mma_kernel<<<grid, 128, NSTAGE*STAGE_BYTES>>>(bias, out);
}